// round 11
// baseline (speedup 1.0000x reference)
#include <cuda_runtime.h>
#include <cuda_fp16.h>
#include <cstdint>

#define HID 100
#define TT 128
#define NSEQ 12288
#define MSEQ 96
#define NCTAS (NSEQ / MSEQ)   // 128
#define NW 13
#define NTH (NW * 32)         // 416
#define KD 112                // 100 h + 4 x + 8 zero pad (7 k16 steps)
#define KK 7
#define ROWS 416              // 13 groups * 32 rows (i,f,g,o × 8 j)
#define SA 120                // W row stride in halves
#define SB 136                // hs col stride in halves (word stride 68: conflict-free)

#define W_HALFS (ROWS * SA)           // 49920
#define H_HALFS (MSEQ * SB)           // 13056 per buffer
// smem byte offsets
#define SM_W    0
#define SM_H0   (W_HALFS * 2)                 // 99840
#define SM_H1   (SM_H0 + H_HALFS * 2)         // 125952
#define SM_BIAS (SM_H1 + H_HALFS * 2)         // 152064
#define SMEM_BYTES (SM_BIAS + 400 * 4)        // 153664

__device__ __half g_W[W_HALFS];
__device__ float  g_bias[400];

__device__ __forceinline__ float tanha(float v){float r;asm("tanh.approx.f32 %0, %1;":"=f"(r):"f"(v));return r;}
__device__ __forceinline__ float sigm(float v){return 0.5f + 0.5f*tanha(0.5f*v);}

// m16n8k16 fp16 mma, fp32 accum, D += A*B
__device__ __forceinline__ void mma16(float* d, const uint32_t* a, uint32_t b0, uint32_t b1){
  asm volatile(
    "mma.sync.aligned.m16n8k16.row.col.f32.f16.f16.f32 "
    "{%0,%1,%2,%3},{%4,%5,%6,%7},{%8,%9},{%0,%1,%2,%3};"
    : "+f"(d[0]),"+f"(d[1]),"+f"(d[2]),"+f"(d[3])
    : "r"(a[0]),"r"(a[1]),"r"(a[2]),"r"(a[3]),"r"(b0),"r"(b1));
}

// Pack W rows: row r -> group w=r/32, q=r%32, gate=q/8, j=8w+q%8.
// cols: k<100 -> W_hh, 100..103 -> W_ih, 104..111 -> 0. j>=100 -> 0.
__global__ void pack_kernel(const float* __restrict__ W_ih, const float* __restrict__ W_hh,
                            const float* __restrict__ b_ih, const float* __restrict__ b_hh){
  int idx = blockIdx.x * blockDim.x + threadIdx.x;
  if (idx < W_HALFS){
    int row = idx / SA, k = idx % SA;
    int w = row >> 5, q = row & 31, gate = q >> 3, j = (w << 3) + (q & 7);
    float v = 0.0f;
    if (j < HID && k < KD){
      if (k < HID)          v = W_hh[(gate * HID + j) * HID + k];
      else if (k < HID + 4) v = W_ih[(gate * HID + j) * 4 + (k - HID)];
    }
    g_W[idx] = __float2half_rn(v);
  }
  if (idx < 400) g_bias[idx] = b_ih[idx] + b_hh[idx];
}

extern __shared__ char smc[];

__global__ void __launch_bounds__(NTH, 1)
lstm_mma(const float* __restrict__ x, float* __restrict__ out){
  __half* Wm  = (__half*)(smc + SM_W);
  __half* hs0 = (__half*)(smc + SM_H0);
  __half* hs1 = (__half*)(smc + SM_H1);
  float*  bsm = (float*)(smc + SM_BIAS);

  const int tid = threadIdx.x;
  const int w = tid >> 5, lane = tid & 31;
  const int tg = lane >> 2, tk = lane & 3;
  const int j = (w << 3) + tg;           // this thread's hidden unit (i,f,g,o owner)
  const int r0 = w << 5;
  const int seq0 = blockIdx.x * MSEQ;

  // fill smem: W staging, bias, zero hs buffers
  { const float4* s = (const float4*)g_W; float4* d = (float4*)Wm;
    for (int i = tid; i < (W_HALFS * 2) / 16; i += NTH) d[i] = s[i]; }
  for (int i = tid; i < 400; i += NTH) bsm[i] = g_bias[i];
  { float4* d0 = (float4*)hs0; float4* d1 = (float4*)hs1;
    for (int i = tid; i < (H_HALFS * 2) / 16; i += NTH){ d0[i] = make_float4(0,0,0,0); d1[i] = make_float4(0,0,0,0);} }

  // x loader: 384 threads own one (seq, feature)
  const bool xl = (tid < MSEQ * 4);
  const int xs = tid >> 2, xf = tid & 3;
  const float* xptr = x + (size_t)(seq0 + xs) * (TT * 4) + xf;
  if (xl) hs0[xs * SB + HID + xf] = __float2half_rn(xptr[0]);
  __syncthreads();

  // ---- hoist A fragments (weights) into registers: invariant across t ----
  uint32_t Af[KK][8];
  {
    const __half* wr = Wm + (r0 + tg) * SA + 2 * tk;
#pragma unroll
    for (int kk = 0; kk < KK; ++kk){
      const int kb = kk * 16;
      Af[kk][0] = *(const uint32_t*)&wr[kb];
      Af[kk][1] = *(const uint32_t*)&wr[kb + 8 * SA];
      Af[kk][2] = *(const uint32_t*)&wr[kb + 8];
      Af[kk][3] = *(const uint32_t*)&wr[kb + 8 * SA + 8];
      Af[kk][4] = *(const uint32_t*)&wr[kb + 16 * SA];
      Af[kk][5] = *(const uint32_t*)&wr[kb + 24 * SA];
      Af[kk][6] = *(const uint32_t*)&wr[kb + 16 * SA + 8];
      Af[kk][7] = *(const uint32_t*)&wr[kb + 24 * SA + 8];
    }
  }

  const int jj = (j < HID) ? j : 0;
  const float bi = bsm[jj], bf = bsm[HID + jj], bg = bsm[2 * HID + jj], bo = bsm[3 * HID + jj];

  float c[24];
#pragma unroll
  for (int i = 0; i < 24; ++i) c[i] = 0.0f;

  for (int t = 0; t < TT; ++t){
    const __half* hsR = (t & 1) ? hs1 : hs0;
    __half*       hsN = (t & 1) ? hs0 : hs1;
    const bool last = (t == TT - 1);
    float xpre;
    if (xl && !last) xpre = xptr[(t + 1) * 4];

#pragma unroll 1
    for (int ph = 0; ph < 2; ++ph){
      float acc[6][8];
#pragma unroll
      for (int n = 0; n < 6; ++n)
#pragma unroll
        for (int e = 0; e < 8; ++e) acc[n][e] = 0.0f;

      const __half* hb = hsR + (ph * 48 + tg) * SB + 2 * tk;
#pragma unroll
      for (int kk = 0; kk < KK; ++kk){
        const int kb = kk * 16;
#pragma unroll
        for (int n = 0; n < 6; ++n){
          uint32_t B0 = *(const uint32_t*)&hb[n * 8 * SB + kb];
          uint32_t B1 = *(const uint32_t*)&hb[n * 8 * SB + kb + 8];
          mma16(acc[n],     Af[kk],     B0, B1);   // rows: i (c0/c1), f (c2/c3)
          mma16(acc[n] + 4, Af[kk] + 4, B0, B1);   // rows: g, o
        }
      }
      if (j < HID){
#pragma unroll
        for (int n = 0; n < 6; ++n)
#pragma unroll
          for (int e = 0; e < 2; ++e){
            const int ci = ph * 12 + n * 2 + e;
            const int col = ph * 48 + n * 8 + 2 * tk + e;
            float ig = sigm(acc[n][0 + e] + bi);
            float fg = sigm(acc[n][2 + e] + bf);
            float gg = tanha(acc[n][4 + e] + bg);
            float og = sigm(acc[n][6 + e] + bo);
            c[ci] = fg * c[ci] + ig * gg;
            float h = og * tanha(c[ci]);
            if (last) out[(size_t)(seq0 + col) * HID + j] = h;
            else      hsN[col * SB + j] = __float2half_rn(h);
          }
      }
    }
    if (xl && !last) hsN[xs * SB + HID + xf] = __float2half_rn(xpre);
    __syncthreads();
  }
}

extern "C" void kernel_launch(void* const* d_in, const int* in_sizes, int n_in,
                              void* d_out, int out_size){
  const float* x    = (const float*)d_in[0];
  const float* W_ih = (const float*)d_in[1];
  const float* W_hh = (const float*)d_in[2];
  const float* b_ih = (const float*)d_in[3];
  const float* b_hh = (const float*)d_in[4];
  float* out = (float*)d_out;

  pack_kernel<<<(W_HALFS + 255) / 256, 256>>>(W_ih, W_hh, b_ih, b_hh);
  cudaFuncSetAttribute(lstm_mma, cudaFuncAttributeMaxDynamicSharedMemorySize, SMEM_BYTES);
  lstm_mma<<<NCTAS, NTH, SMEM_BYTES>>>(x, out);
}

// round 12
// speedup vs baseline: 1.7066x; 1.7066x over previous
#include <cuda_runtime.h>
#include <cuda_fp16.h>
#include <cstdint>

#define HID 100
#define TT 128
#define NSEQ 12288
#define MSEQ 96
#define NCTAS (NSEQ / MSEQ)   // 128
#define NW 13
#define NTH (NW * 32)         // 416
#define KD 112                // 100 h + 4 x + 8 zero pad (7 k16 steps)
#define KK 7
#define ROWS 416              // 13 groups * 32 rows (i,f,g,o × 8 j)
#define SA 120                // W row stride in halves
#define SB 136                // hs col stride in halves (word stride 68: conflict-free)

#define W_HALFS (ROWS * SA)           // 49920
#define H_HALFS (MSEQ * SB)           // 13056 per buffer
// smem byte offsets
#define SM_W    0
#define SM_H0   (W_HALFS * 2)                 // 99840
#define SM_H1   (SM_H0 + H_HALFS * 2)         // 125952
#define SM_BIAS (SM_H1 + H_HALFS * 2)         // 152064
#define SMEM_BYTES (SM_BIAS + 400 * 4)        // 153664

__device__ __half g_W[W_HALFS];
__device__ float  g_bias[400];

__device__ __forceinline__ float tanha(float v){float r;asm("tanh.approx.f32 %0, %1;":"=f"(r):"f"(v));return r;}
__device__ __forceinline__ float sigm(float v){return 0.5f + 0.5f*tanha(0.5f*v);}

// m16n8k16 fp16 mma, fp32 accum, D += A*B
__device__ __forceinline__ void mma16(float* d, const uint32_t* a, uint32_t b0, uint32_t b1){
  asm volatile(
    "mma.sync.aligned.m16n8k16.row.col.f32.f16.f16.f32 "
    "{%0,%1,%2,%3},{%4,%5,%6,%7},{%8,%9},{%0,%1,%2,%3};"
    : "+f"(d[0]),"+f"(d[1]),"+f"(d[2]),"+f"(d[3])
    : "r"(a[0]),"r"(a[1]),"r"(a[2]),"r"(a[3]),"r"(b0),"r"(b1));
}

// Pack W rows: row r -> group w=r/32, q=r%32, gate=q/8, j=8w+q%8.
// cols: k<100 -> W_hh, 100..103 -> W_ih, 104..111 -> 0. j>=100 -> 0.
__global__ void pack_kernel(const float* __restrict__ W_ih, const float* __restrict__ W_hh,
                            const float* __restrict__ b_ih, const float* __restrict__ b_hh){
  int idx = blockIdx.x * blockDim.x + threadIdx.x;
  if (idx < W_HALFS){
    int row = idx / SA, k = idx % SA;
    int w = row >> 5, q = row & 31, gate = q >> 3, j = (w << 3) + (q & 7);
    float v = 0.0f;
    if (j < HID && k < KD){
      if (k < HID)          v = W_hh[(gate * HID + j) * HID + k];
      else if (k < HID + 4) v = W_ih[(gate * HID + j) * 4 + (k - HID)];
    }
    g_W[idx] = __float2half_rn(v);
  }
  if (idx < 400) g_bias[idx] = b_ih[idx] + b_hh[idx];
}

extern __shared__ char smc[];

__global__ void __launch_bounds__(NTH, 1)
lstm_mma(const float* __restrict__ x, float* __restrict__ out){
  __half* Wm  = (__half*)(smc + SM_W);
  __half* hs0 = (__half*)(smc + SM_H0);
  __half* hs1 = (__half*)(smc + SM_H1);
  float*  bsm = (float*)(smc + SM_BIAS);

  const int tid = threadIdx.x;
  const int w = tid >> 5, lane = tid & 31;
  const int tg = lane >> 2, tk = lane & 3;
  const int j = (w << 3) + tg;           // this thread's hidden unit (i,f,g,o owner)
  const int r0 = w << 5;
  const int seq0 = blockIdx.x * MSEQ;

  // fill smem: W staging, bias, zero hs buffers
  { const float4* s = (const float4*)g_W; float4* d = (float4*)Wm;
    for (int i = tid; i < (W_HALFS * 2) / 16; i += NTH) d[i] = s[i]; }
  for (int i = tid; i < 400; i += NTH) bsm[i] = g_bias[i];
  { float4* d0 = (float4*)hs0; float4* d1 = (float4*)hs1;
    for (int i = tid; i < (H_HALFS * 2) / 16; i += NTH){ d0[i] = make_float4(0,0,0,0); d1[i] = make_float4(0,0,0,0);} }

  // x loader: 384 threads own one (seq, feature)
  const bool xl = (tid < MSEQ * 4);
  const int xs = tid >> 2, xf = tid & 3;
  const float* xptr = x + (size_t)(seq0 + xs) * (TT * 4) + xf;
  if (xl) hs0[xs * SB + HID + xf] = __float2half_rn(xptr[0]);
  __syncthreads();

  // ---- hoist A fragments (weights) into registers: invariant across t ----
  uint32_t Af[KK][8];
  {
    const __half* wr = Wm + (r0 + tg) * SA + 2 * tk;
#pragma unroll
    for (int kk = 0; kk < KK; ++kk){
      const int kb = kk * 16;
      Af[kk][0] = *(const uint32_t*)&wr[kb];
      Af[kk][1] = *(const uint32_t*)&wr[kb + 8 * SA];
      Af[kk][2] = *(const uint32_t*)&wr[kb + 8];
      Af[kk][3] = *(const uint32_t*)&wr[kb + 8 * SA + 8];
      Af[kk][4] = *(const uint32_t*)&wr[kb + 16 * SA];
      Af[kk][5] = *(const uint32_t*)&wr[kb + 24 * SA];
      Af[kk][6] = *(const uint32_t*)&wr[kb + 16 * SA + 8];
      Af[kk][7] = *(const uint32_t*)&wr[kb + 24 * SA + 8];
    }
  }

  const int jj = (j < HID) ? j : 0;
  const float bi = bsm[jj], bf = bsm[HID + jj], bg = bsm[2 * HID + jj], bo = bsm[3 * HID + jj];

  float c[24];
#pragma unroll
  for (int i = 0; i < 24; ++i) c[i] = 0.0f;

  for (int t = 0; t < TT; ++t){
    const __half* hsR = (t & 1) ? hs1 : hs0;
    __half*       hsN = (t & 1) ? hs0 : hs1;
    const bool last = (t == TT - 1);
    float xpre;
    if (xl && !last) xpre = xptr[(t + 1) * 4];

    // 4 phases of 24 seq columns: live accumulators = 24 regs (3 n-tiles)
#pragma unroll 1
    for (int ph = 0; ph < 4; ++ph){
      float acc[3][8];
#pragma unroll
      for (int n = 0; n < 3; ++n)
#pragma unroll
        for (int e = 0; e < 8; ++e) acc[n][e] = 0.0f;

      const __half* hb = hsR + (ph * 24 + tg) * SB + 2 * tk;
#pragma unroll
      for (int kk = 0; kk < KK; ++kk){
        const int kb = kk * 16;
#pragma unroll
        for (int n = 0; n < 3; ++n){
          uint32_t B0 = *(const uint32_t*)&hb[n * 8 * SB + kb];
          uint32_t B1 = *(const uint32_t*)&hb[n * 8 * SB + kb + 8];
          mma16(acc[n],     Af[kk],     B0, B1);   // rows: i (c0/c1), f (c2/c3)
          mma16(acc[n] + 4, Af[kk] + 4, B0, B1);   // rows: g, o
        }
      }
      if (j < HID){
#pragma unroll
        for (int n = 0; n < 3; ++n)
#pragma unroll
          for (int e = 0; e < 2; ++e){
            const int ci = ph * 6 + n * 2 + e;
            const int col = ph * 24 + n * 8 + 2 * tk + e;
            float ig = sigm(acc[n][0 + e] + bi);
            float fg = sigm(acc[n][2 + e] + bf);
            float gg = tanha(acc[n][4 + e] + bg);
            float og = sigm(acc[n][6 + e] + bo);
            c[ci] = fg * c[ci] + ig * gg;
            float h = og * tanha(c[ci]);
            if (last) out[(size_t)(seq0 + col) * HID + j] = h;
            else      hsN[col * SB + j] = __float2half_rn(h);
          }
      }
    }
    if (xl && !last) hsN[xs * SB + HID + xf] = __float2half_rn(xpre);
    __syncthreads();
  }
}

extern "C" void kernel_launch(void* const* d_in, const int* in_sizes, int n_in,
                              void* d_out, int out_size){
  const float* x    = (const float*)d_in[0];
  const float* W_ih = (const float*)d_in[1];
  const float* W_hh = (const float*)d_in[2];
  const float* b_ih = (const float*)d_in[3];
  const float* b_hh = (const float*)d_in[4];
  float* out = (float*)d_out;

  pack_kernel<<<(W_HALFS + 255) / 256, 256>>>(W_ih, W_hh, b_ih, b_hh);
  cudaFuncSetAttribute(lstm_mma, cudaFuncAttributeMaxDynamicSharedMemorySize, SMEM_BYTES);
  lstm_mma<<<NCTAS, NTH, SMEM_BYTES>>>(x, out);
}

// round 13
// speedup vs baseline: 1.7242x; 1.0103x over previous
#include <cuda_runtime.h>
#include <cuda_fp16.h>
#include <cstdint>

#define HID 100
#define TT 128
#define NSEQ 12288
#define MSEQ 96
#define NCTAS (NSEQ / MSEQ)   // 128
#define NW 13
#define NTH (NW * 32)         // 416
#define KD 112                // 100 h + 4 x + 8 zero pad (7 k16 steps)
#define KK 7
#define ROWS 416              // 13 groups * 32 rows (i,f,g,o × 8 j)
#define SA 120                // W row stride in halves
#define SB 136                // hs col stride in halves (word stride 68: conflict-free)

#define W_HALFS (ROWS * SA)           // 49920
#define H_HALFS (MSEQ * SB)           // 13056 per buffer
// smem byte offsets
#define SM_W    0
#define SM_H0   (W_HALFS * 2)                 // 99840
#define SM_H1   (SM_H0 + H_HALFS * 2)         // 125952
#define SM_BIAS (SM_H1 + H_HALFS * 2)         // 152064
#define SMEM_BYTES (SM_BIAS + 400 * 4)        // 153664

__device__ __half g_W[W_HALFS];
__device__ float  g_bias[400];

__device__ __forceinline__ float tanha(float v){float r;asm("tanh.approx.f32 %0, %1;":"=f"(r):"f"(v));return r;}
__device__ __forceinline__ float sigm(float v){return 0.5f + 0.5f*tanha(0.5f*v);}
__device__ __forceinline__ __half2 tanh2(__half2 v){
  uint32_t x = *reinterpret_cast<uint32_t*>(&v), r;
  asm("tanh.approx.f16x2 %0, %1;" : "=r"(r) : "r"(x));
  return *reinterpret_cast<__half2*>(&r);
}

// m16n8k16 fp16 mma, fp32 accum, D += A*B
__device__ __forceinline__ void mma16(float* d, const uint32_t* a, uint32_t b0, uint32_t b1){
  asm volatile(
    "mma.sync.aligned.m16n8k16.row.col.f32.f16.f16.f32 "
    "{%0,%1,%2,%3},{%4,%5,%6,%7},{%8,%9},{%0,%1,%2,%3};"
    : "+f"(d[0]),"+f"(d[1]),"+f"(d[2]),"+f"(d[3])
    : "r"(a[0]),"r"(a[1]),"r"(a[2]),"r"(a[3]),"r"(b0),"r"(b1));
}

// Pack W rows: row r -> group w=r/32, q=r%32, gate=q/8, j=8w+q%8.
// cols: k<100 -> W_hh, 100..103 -> W_ih, 104..111 -> 0. j>=100 -> 0.
__global__ void pack_kernel(const float* __restrict__ W_ih, const float* __restrict__ W_hh,
                            const float* __restrict__ b_ih, const float* __restrict__ b_hh){
  int idx = blockIdx.x * blockDim.x + threadIdx.x;
  if (idx < W_HALFS){
    int row = idx / SA, k = idx % SA;
    int w = row >> 5, q = row & 31, gate = q >> 3, j = (w << 3) + (q & 7);
    float v = 0.0f;
    if (j < HID && k < KD){
      if (k < HID)          v = W_hh[(gate * HID + j) * HID + k];
      else if (k < HID + 4) v = W_ih[(gate * HID + j) * 4 + (k - HID)];
    }
    g_W[idx] = __float2half_rn(v);
  }
  if (idx < 400) g_bias[idx] = b_ih[idx] + b_hh[idx];
}

extern __shared__ char smc[];

__global__ void __launch_bounds__(NTH, 1)
lstm_mma(const float* __restrict__ x, float* __restrict__ out){
  __half* Wm  = (__half*)(smc + SM_W);
  __half* hs0 = (__half*)(smc + SM_H0);
  __half* hs1 = (__half*)(smc + SM_H1);
  float*  bsm = (float*)(smc + SM_BIAS);

  const int tid = threadIdx.x;
  const int w = tid >> 5, lane = tid & 31;
  const int tg = lane >> 2, tk = lane & 3;
  const int j = (w << 3) + tg;           // this thread's hidden unit (i,f,g,o owner)
  const int r0 = w << 5;
  const int seq0 = blockIdx.x * MSEQ;

  // fill smem: W staging, bias, zero hs buffers
  { const float4* s = (const float4*)g_W; float4* d = (float4*)Wm;
    for (int i = tid; i < (W_HALFS * 2) / 16; i += NTH) d[i] = s[i]; }
  for (int i = tid; i < 400; i += NTH) bsm[i] = g_bias[i];
  { float4* d0 = (float4*)hs0; float4* d1 = (float4*)hs1;
    for (int i = tid; i < (H_HALFS * 2) / 16; i += NTH){ d0[i] = make_float4(0,0,0,0); d1[i] = make_float4(0,0,0,0);} }

  // x loader: 384 threads own one (seq, feature)
  const bool xl = (tid < MSEQ * 4);
  const int xs = tid >> 2, xf = tid & 3;
  const float* xptr = x + (size_t)(seq0 + xs) * (TT * 4) + xf;
  if (xl) hs0[xs * SB + HID + xf] = __float2half_rn(xptr[0]);
  __syncthreads();

  // ---- hoist A fragments (weights) into registers: invariant across t ----
  uint32_t Af[KK][8];
  {
    const __half* wr = Wm + (r0 + tg) * SA + 2 * tk;
#pragma unroll
    for (int kk = 0; kk < KK; ++kk){
      const int kb = kk * 16;
      Af[kk][0] = *(const uint32_t*)&wr[kb];
      Af[kk][1] = *(const uint32_t*)&wr[kb + 8 * SA];
      Af[kk][2] = *(const uint32_t*)&wr[kb + 8];
      Af[kk][3] = *(const uint32_t*)&wr[kb + 8 * SA + 8];
      Af[kk][4] = *(const uint32_t*)&wr[kb + 16 * SA];
      Af[kk][5] = *(const uint32_t*)&wr[kb + 24 * SA];
      Af[kk][6] = *(const uint32_t*)&wr[kb + 16 * SA + 8];
      Af[kk][7] = *(const uint32_t*)&wr[kb + 24 * SA + 8];
    }
  }

  const int jj = (j < HID) ? j : 0;
  const float bi = bsm[jj], bf = bsm[HID + jj], bg = bsm[2 * HID + jj], bo = bsm[3 * HID + jj];
  const float bi2 = 0.5f * bi, bf2 = 0.5f * bf, bo2 = 0.5f * bo;
  const __half2 H05 = __floats2half2_rn(0.5f, 0.5f);

  float c[24];
#pragma unroll
  for (int i = 0; i < 24; ++i) c[i] = 0.0f;

  for (int t = 0; t < TT; ++t){
    const __half* hsR = (t & 1) ? hs1 : hs0;
    __half*       hsN = (t & 1) ? hs0 : hs1;
    const bool last = (t == TT - 1);
    float xpre;
    if (xl && !last) xpre = xptr[(t + 1) * 4];

    // 4 phases of 24 seq columns: live accumulators = 24 regs (3 n-tiles)
#pragma unroll 1
    for (int ph = 0; ph < 4; ++ph){
      float acc[3][8];
#pragma unroll
      for (int n = 0; n < 3; ++n)
#pragma unroll
        for (int e = 0; e < 8; ++e) acc[n][e] = 0.0f;

      const __half* hb = hsR + (ph * 24 + tg) * SB + 2 * tk;
#pragma unroll
      for (int kk = 0; kk < KK; ++kk){
        const int kb = kk * 16;
#pragma unroll
        for (int n = 0; n < 3; ++n){
          uint32_t B0 = *(const uint32_t*)&hb[n * 8 * SB + kb];
          uint32_t B1 = *(const uint32_t*)&hb[n * 8 * SB + kb + 8];
          mma16(acc[n],     Af[kk],     B0, B1);   // rows: i (c0/c1), f (c2/c3)
          mma16(acc[n] + 4, Af[kk] + 4, B0, B1);   // rows: g, o
        }
      }
      if (j < HID){
#pragma unroll
        for (int n = 0; n < 3; ++n){
          const int ci  = ph * 6 + n * 2;
          const int col = ph * 24 + n * 8 + 2 * tk;
          if (!last){
            // packed f16x2 activations over the (e=0, e=1) seq pair; c stays fp32
            __half2 pi = __floats2half2_rn(fmaf(acc[n][0], 0.5f, bi2), fmaf(acc[n][1], 0.5f, bi2));
            __half2 pf = __floats2half2_rn(fmaf(acc[n][2], 0.5f, bf2), fmaf(acc[n][3], 0.5f, bf2));
            __half2 pg = __floats2half2_rn(acc[n][4] + bg,             acc[n][5] + bg);
            __half2 po = __floats2half2_rn(fmaf(acc[n][6], 0.5f, bo2), fmaf(acc[n][7], 0.5f, bo2));
            __half2 si = __hfma2(tanh2(pi), H05, H05);
            __half2 sf = __hfma2(tanh2(pf), H05, H05);
            __half2 tg2 = tanh2(pg);
            __half2 so = __hfma2(tanh2(po), H05, H05);
            float2 fi = __half22float2(si);
            float2 ff = __half22float2(sf);
            float2 fg = __half22float2(tg2);
            c[ci]     = ff.x * c[ci]     + fi.x * fg.x;
            c[ci + 1] = ff.y * c[ci + 1] + fi.y * fg.y;
            __half2 pc = __floats2half2_rn(c[ci], c[ci + 1]);
            __half2 h2 = __hmul2(so, tanh2(pc));
            hsN[col * SB + j]       = __low2half(h2);
            hsN[(col + 1) * SB + j] = __high2half(h2);
          } else {
            // final step: fp32 path so the output is not fp16-quantized
#pragma unroll
            for (int e = 0; e < 2; ++e){
              float ig = sigm(acc[n][0 + e] + bi);
              float fg2 = sigm(acc[n][2 + e] + bf);
              float gg = tanha(acc[n][4 + e] + bg);
              float og = sigm(acc[n][6 + e] + bo);
              c[ci + e] = fg2 * c[ci + e] + ig * gg;
              out[(size_t)(seq0 + col + e) * HID + j] = og * tanha(c[ci + e]);
            }
          }
        }
      }
    }
    if (xl && !last) hsN[xs * SB + HID + xf] = __float2half_rn(xpre);
    __syncthreads();
  }
}

extern "C" void kernel_launch(void* const* d_in, const int* in_sizes, int n_in,
                              void* d_out, int out_size){
  const float* x    = (const float*)d_in[0];
  const float* W_ih = (const float*)d_in[1];
  const float* W_hh = (const float*)d_in[2];
  const float* b_ih = (const float*)d_in[3];
  const float* b_hh = (const float*)d_in[4];
  float* out = (float*)d_out;

  pack_kernel<<<(W_HALFS + 255) / 256, 256>>>(W_ih, W_hh, b_ih, b_hh);
  cudaFuncSetAttribute(lstm_mma, cudaFuncAttributeMaxDynamicSharedMemorySize, SMEM_BYTES);
  lstm_mma<<<NCTAS, NTH, SMEM_BYTES>>>(x, out);
}